// round 3
// baseline (speedup 1.0000x reference)
#include <cuda_runtime.h>
#include <cuda_bf16.h>
#include <math.h>

// Problem shapes (fixed by the reference)
#define BATCH 16
#define KQ    512      // query rows
#define NK    2048     // key rows per batch
#define DIM   1024     // embedding dim

// ---------------- scratch (no cudaMalloc allowed) ----------------
__device__ float g_qW[KQ * DIM];                       // 2 MB
__device__ float g_att_scratch[BATCH * KQ * NK];       // 64 MB (used only if att not in d_out)
__device__ int   g_mask_kind;                          // 0=int32, 1=uint8, 2=float32

// ---------------- mask dtype detection ----------------
// Inspect first 4096 bytes; classify layout by which (offset % 4) classes hold nonzeros.
__global__ void detect_mask_kind(const unsigned char* __restrict__ m)
{
    if (threadIdx.x != 0 || blockIdx.x != 0) return;
    int cnt[4] = {0, 0, 0, 0};
    for (int i = 0; i < 4096; i++)
        if (m[i] != 0) cnt[i & 3]++;
    int kind;
    if (cnt[1] > 0)                         kind = 1;  // uint8 bool: ~50% nonzero at every offset
    else if (cnt[2] > 0 || cnt[3] > 0)      kind = 2;  // float32 1.0f: 0x3F800000 -> offsets 2,3
    else                                    kind = 0;  // int32 bool: nonzero only at offset 0
    g_mask_kind = kind;
}

// ---------------- tiled fp32 GEMM kernels ----------------
// 128x128 tile, KB=8, 256 threads, 8x8 per thread. All dims multiples of 128.
#define TILE 128
#define KB   8

// C[M,N] = alpha * A[M,Kd] (row-major) * B[Kd,N] (row-major), batched via z
__global__ __launch_bounds__(256) void gemm_nn(
    const float* __restrict__ A, const float* __restrict__ B, float* __restrict__ C,
    int M, int N, int Kd,
    long sA, long sB, long sC, float alpha)
{
    int bz = blockIdx.z;
    A += (long)bz * sA; B += (long)bz * sB; C += (long)bz * sC;

    __shared__ float As[KB][TILE];
    __shared__ float Bs[KB][TILE];

    int tid = threadIdx.x;
    int m0 = blockIdx.y * TILE;
    int n0 = blockIdx.x * TILE;
    int tm = (tid >> 4) * 8;   // 0..120
    int tn = (tid & 15) * 8;   // 0..120

    float acc[8][8];
    #pragma unroll
    for (int i = 0; i < 8; i++)
        #pragma unroll
        for (int j = 0; j < 8; j++) acc[i][j] = 0.f;

    for (int k0 = 0; k0 < Kd; k0 += KB) {
        // A tile: 128 rows x 8 k (transposed store)
        {
            int row = tid >> 1;
            int seg = (tid & 1) * 4;
            float4 v = *reinterpret_cast<const float4*>(&A[(long)(m0 + row) * Kd + k0 + seg]);
            As[seg + 0][row] = v.x; As[seg + 1][row] = v.y;
            As[seg + 2][row] = v.z; As[seg + 3][row] = v.w;
        }
        // B tile: 8 k-rows x 128 cols (direct, coalesced)
        {
            int row = tid >> 5;
            int col = (tid & 31) * 4;
            float4 v = *reinterpret_cast<const float4*>(&B[(long)(k0 + row) * N + n0 + col]);
            *reinterpret_cast<float4*>(&Bs[row][col]) = v;
        }
        __syncthreads();
        #pragma unroll
        for (int kk = 0; kk < KB; kk++) {
            float a[8], b[8];
            #pragma unroll
            for (int i = 0; i < 8; i++) a[i] = As[kk][tm + i];
            #pragma unroll
            for (int j = 0; j < 8; j++) b[j] = Bs[kk][tn + j];
            #pragma unroll
            for (int i = 0; i < 8; i++)
                #pragma unroll
                for (int j = 0; j < 8; j++) acc[i][j] += a[i] * b[j];
        }
        __syncthreads();
    }

    #pragma unroll
    for (int i = 0; i < 8; i++) {
        float4 v0 = make_float4(acc[i][0]*alpha, acc[i][1]*alpha, acc[i][2]*alpha, acc[i][3]*alpha);
        float4 v1 = make_float4(acc[i][4]*alpha, acc[i][5]*alpha, acc[i][6]*alpha, acc[i][7]*alpha);
        float* cp = &C[(long)(m0 + tm + i) * N + n0 + tn];
        *reinterpret_cast<float4*>(cp)     = v0;
        *reinterpret_cast<float4*>(cp + 4) = v1;
    }
}

// C[M,N] = A[M,Kd] (row-major) * B[N,Kd]^T (B row-major, K-contiguous), batched via z
__global__ __launch_bounds__(256) void gemm_nt(
    const float* __restrict__ A, const float* __restrict__ B, float* __restrict__ C,
    int M, int N, int Kd,
    long sA, long sB, long sC)
{
    int bz = blockIdx.z;
    A += (long)bz * sA; B += (long)bz * sB; C += (long)bz * sC;

    __shared__ float As[KB][TILE];
    __shared__ float Bs[KB][TILE];

    int tid = threadIdx.x;
    int m0 = blockIdx.y * TILE;
    int n0 = blockIdx.x * TILE;
    int tm = (tid >> 4) * 8;
    int tn = (tid & 15) * 8;

    float acc[8][8];
    #pragma unroll
    for (int i = 0; i < 8; i++)
        #pragma unroll
        for (int j = 0; j < 8; j++) acc[i][j] = 0.f;

    for (int k0 = 0; k0 < Kd; k0 += KB) {
        {
            int row = tid >> 1;
            int seg = (tid & 1) * 4;
            float4 v = *reinterpret_cast<const float4*>(&A[(long)(m0 + row) * Kd + k0 + seg]);
            As[seg + 0][row] = v.x; As[seg + 1][row] = v.y;
            As[seg + 2][row] = v.z; As[seg + 3][row] = v.w;
        }
        {
            int row = tid >> 1;             // n within tile
            int seg = (tid & 1) * 4;        // k segment
            float4 v = *reinterpret_cast<const float4*>(&B[(long)(n0 + row) * Kd + k0 + seg]);
            Bs[seg + 0][row] = v.x; Bs[seg + 1][row] = v.y;
            Bs[seg + 2][row] = v.z; Bs[seg + 3][row] = v.w;
        }
        __syncthreads();
        #pragma unroll
        for (int kk = 0; kk < KB; kk++) {
            float a[8], b[8];
            #pragma unroll
            for (int i = 0; i < 8; i++) a[i] = As[kk][tm + i];
            #pragma unroll
            for (int j = 0; j < 8; j++) b[j] = Bs[kk][tn + j];
            #pragma unroll
            for (int i = 0; i < 8; i++)
                #pragma unroll
                for (int j = 0; j < 8; j++) acc[i][j] += a[i] * b[j];
        }
        __syncthreads();
    }

    #pragma unroll
    for (int i = 0; i < 8; i++) {
        float4 v0 = make_float4(acc[i][0], acc[i][1], acc[i][2], acc[i][3]);
        float4 v1 = make_float4(acc[i][4], acc[i][5], acc[i][6], acc[i][7]);
        float* cp = &C[(long)(m0 + tm + i) * N + n0 + tn];
        *reinterpret_cast<float4*>(cp)     = v0;
        *reinterpret_cast<float4*>(cp + 4) = v1;
    }
}

// ---------------- fused mask + softmax over rows of length NK ----------------
// one block (256 threads) per (b,k) row; 8 elems per thread held in registers
__global__ __launch_bounds__(256) void mask_softmax(
    float* __restrict__ att, const void* __restrict__ mask_raw)
{
    long row = blockIdx.x;                 // b*KQ + k
    float* p = att + row * (long)NK;
    int tid = threadIdx.x;
    int kind = g_mask_kind;

    const unsigned char* m8  = (const unsigned char*)mask_raw + row * (long)NK;
    const int*           m32 = (const int*)mask_raw           + row * (long)NK;
    const float*         mf  = (const float*)mask_raw         + row * (long)NK;

    float v[8];
    float lmax = -INFINITY;
    #pragma unroll
    for (int i = 0; i < 8; i++) {
        int idx = tid + i * 256;
        bool keep;
        if (kind == 0)      keep = (m32[idx] != 0);
        else if (kind == 1) keep = (m8[idx] != 0);
        else                keep = (mf[idx] != 0.0f);
        float s = keep ? p[idx] : -INFINITY;
        v[i] = s;
        lmax = fmaxf(lmax, s);
    }

    __shared__ float red[8];
    #pragma unroll
    for (int o = 16; o > 0; o >>= 1)
        lmax = fmaxf(lmax, __shfl_xor_sync(0xffffffffu, lmax, o));
    if ((tid & 31) == 0) red[tid >> 5] = lmax;
    __syncthreads();
    float rmax = fmaxf(fmaxf(fmaxf(red[0], red[1]), fmaxf(red[2], red[3])),
                       fmaxf(fmaxf(red[4], red[5]), fmaxf(red[6], red[7])));
    __syncthreads();

    float lsum = 0.f;
    #pragma unroll
    for (int i = 0; i < 8; i++) {
        float e = (v[i] == -INFINITY) ? 0.f : __expf(v[i] - rmax);
        v[i] = e;
        lsum += e;
    }
    #pragma unroll
    for (int o = 16; o > 0; o >>= 1)
        lsum += __shfl_xor_sync(0xffffffffu, lsum, o);
    if ((tid & 31) == 0) red[tid >> 5] = lsum;
    __syncthreads();
    float rsum = red[0] + red[1] + red[2] + red[3] + red[4] + red[5] + red[6] + red[7];
    float inv = (rsum > 0.f) ? (1.f / rsum) : 0.f;

    #pragma unroll
    for (int i = 0; i < 8; i++) p[tid + i * 256] = v[i] * inv;
}

// ---------------- launcher ----------------
extern "C" void kernel_launch(void* const* d_in, const int* in_sizes, int n_in,
                              void* d_out, int out_size)
{
    const float* query = (const float*)d_in[0];          // [KQ, DIM]
    const float* key   = (const float*)d_in[1];          // [BATCH, NK, DIM]
    const float* W     = (const float*)d_in[2];          // [DIM, DIM]
    const void*  mask  = d_in[3];                        // [BATCH, KQ, NK] bool (dtype detected)

    float* out_ptr = (float*)d_out;                      // [BATCH, KQ, DIM] first
    const long outBKD = (long)BATCH * KQ * DIM;

    float* qW;
    cudaGetSymbolAddress((void**)&qW, g_qW);
    float* att_ptr;
    if ((long)out_size > outBKD) {
        att_ptr = out_ptr + outBKD;                      // att is part of the output tuple
    } else {
        cudaGetSymbolAddress((void**)&att_ptr, g_att_scratch);
    }

    const float inv_sqrt_d = 1.0f / 32.0f;               // 1/sqrt(1024)

    // 0) detect mask element layout (writes g_mask_kind)
    detect_mask_kind<<<1, 1>>>((const unsigned char*)mask);

    // 1) qW = (query @ W) / sqrt(d)   [KQ, DIM]
    {
        dim3 grid(DIM / TILE, KQ / TILE, 1);
        gemm_nn<<<grid, 256>>>(query, W, qW, KQ, DIM, DIM, 0, 0, 0, inv_sqrt_d);
    }
    // 2) scores[b] = qW @ key[b]^T    [KQ, NK] per batch
    {
        dim3 grid(NK / TILE, KQ / TILE, BATCH);
        gemm_nt<<<grid, 256>>>(qW, key, att_ptr, KQ, NK, DIM,
                               0L, (long)NK * DIM, (long)KQ * NK);
    }
    // 3) mask + softmax in place
    {
        mask_softmax<<<BATCH * KQ, 256>>>(att_ptr, mask);
    }
    // 4) out[b] = att[b] @ key[b]     [KQ, DIM] per batch
    {
        dim3 grid(DIM / TILE, KQ / TILE, BATCH);
        gemm_nn<<<grid, 256>>>(att_ptr, key, out_ptr, KQ, DIM, NK,
                               (long)KQ * NK, (long)NK * DIM, (long)KQ * DIM, 1.0f);
    }
}

// round 5
// speedup vs baseline: 2.4965x; 2.4965x over previous
#include <cuda_runtime.h>
#include <cuda_bf16.h>
#include <math.h>
#include <stdint.h>

// Problem shapes (fixed by the reference)
#define BATCH 16
#define KQ    512
#define NK    2048
#define DIM   1024

// ---------------- scratch (no cudaMalloc allowed) ----------------
__device__ float g_qW[KQ * DIM];                   // 2 MB
__device__ float g_att_scratch[BATCH * KQ * NK];   // 64 MB (if att not in d_out)
__device__ int   g_mask_kind;                      // 0=int32, 1=uint8, 2=float32

// ---------------- helpers ----------------
__device__ __forceinline__ float rna_tf32(float x) {
    float y;
    asm("cvt.rna.tf32.f32 %0, %1;" : "=f"(y) : "f"(x));
    return y;
}
__device__ __forceinline__ float4 rna4(float4 v) {
    v.x = rna_tf32(v.x); v.y = rna_tf32(v.y);
    v.z = rna_tf32(v.z); v.w = rna_tf32(v.w);
    return v;
}
__device__ __forceinline__ void mma_tf32(float* c, const uint32_t* a, const uint32_t* b) {
    asm volatile(
        "mma.sync.aligned.m16n8k8.row.col.f32.tf32.tf32.f32 "
        "{%0,%1,%2,%3}, {%4,%5,%6,%7}, {%8,%9}, {%0,%1,%2,%3};"
        : "+f"(c[0]), "+f"(c[1]), "+f"(c[2]), "+f"(c[3])
        : "r"(a[0]), "r"(a[1]), "r"(a[2]), "r"(a[3]), "r"(b[0]), "r"(b[1]));
}

// =====================================================================
// tf32 mma.sync GEMM, NT variant:
//   C[M,N] = alpha * A[M,Kd] (row-major) * B[N,Kd]^T   (both K-contiguous)
// Block 128x128, 8 warps (2x4), warp tile 64x32, K-chunk 16.
// Single smem stage + register prefetch of next chunk.
// =====================================================================
#define SA_STRIDE 20   // 16 cols + pad: conflict-free fragment reads
#define SB_STRIDE 136  // NN B tile: 128 cols + pad

__global__ void __launch_bounds__(256) gemm_nt_mma(
    const float* __restrict__ A, const float* __restrict__ B, float* __restrict__ C,
    int Kd, int lda, int ldb, int ldc, long sA, long sB, long sC, float alpha)
{
    __shared__ float As[128][SA_STRIDE];
    __shared__ float Bs[128][SA_STRIDE];

    const int tid  = threadIdx.x;
    const int wid  = tid >> 5;
    const int lane = tid & 31;
    const int wm   = wid & 1;        // 0..1  -> 64-row half
    const int wn   = wid >> 1;       // 0..3  -> 32-col quarter
    const int grp  = lane >> 2;      // 0..7
    const int tig  = lane & 3;       // 0..3

    A += (long)blockIdx.z * sA + (long)blockIdx.y * 128 * lda;
    B += (long)blockIdx.z * sB + (long)blockIdx.x * 128 * ldb;
    C += (long)blockIdx.z * sC + (long)blockIdx.y * 128 * ldc + (long)blockIdx.x * 128;

    const int arow = tid >> 1;           // 0..127
    const int acol = (tid & 1) * 8;      // 0 or 8

    float acc[4][4][4];
    #pragma unroll
    for (int i = 0; i < 4; i++)
        #pragma unroll
        for (int j = 0; j < 4; j++)
            #pragma unroll
            for (int t = 0; t < 4; t++) acc[i][j][t] = 0.f;

    const int NCH = Kd >> 4;
    float4 pa0, pa1, pb0, pb1;
    // prefetch chunk 0
    pa0 = *(const float4*)(A + (long)arow * lda + acol);
    pa1 = *(const float4*)(A + (long)arow * lda + acol + 4);
    pb0 = *(const float4*)(B + (long)arow * ldb + acol);
    pb1 = *(const float4*)(B + (long)arow * ldb + acol + 4);

    for (int kc = 0; kc < NCH; kc++) {
        __syncthreads();   // previous chunk's MMAs done reading smem
        *(float4*)&As[arow][acol]     = rna4(pa0);
        *(float4*)&As[arow][acol + 4] = rna4(pa1);
        *(float4*)&Bs[arow][acol]     = rna4(pb0);
        *(float4*)&Bs[arow][acol + 4] = rna4(pb1);
        __syncthreads();

        if (kc + 1 < NCH) {
            const float* An = A + (long)(kc + 1) * 16;
            const float* Bn = B + (long)(kc + 1) * 16;
            pa0 = *(const float4*)(An + (long)arow * lda + acol);
            pa1 = *(const float4*)(An + (long)arow * lda + acol + 4);
            pb0 = *(const float4*)(Bn + (long)arow * ldb + acol);
            pb1 = *(const float4*)(Bn + (long)arow * ldb + acol + 4);
        }

        #pragma unroll
        for (int ks = 0; ks < 2; ks++) {
            const int k0 = ks * 8;
            uint32_t afr[4][4], bfr[4][2];
            #pragma unroll
            for (int mt = 0; mt < 4; mt++) {
                int r0 = wm * 64 + mt * 16 + grp;
                afr[mt][0] = __float_as_uint(As[r0][k0 + tig]);
                afr[mt][1] = __float_as_uint(As[r0 + 8][k0 + tig]);
                afr[mt][2] = __float_as_uint(As[r0][k0 + tig + 4]);
                afr[mt][3] = __float_as_uint(As[r0 + 8][k0 + tig + 4]);
            }
            #pragma unroll
            for (int nt = 0; nt < 4; nt++) {
                int n0 = wn * 32 + nt * 8 + grp;
                bfr[nt][0] = __float_as_uint(Bs[n0][k0 + tig]);
                bfr[nt][1] = __float_as_uint(Bs[n0][k0 + tig + 4]);
            }
            #pragma unroll
            for (int mt = 0; mt < 4; mt++)
                #pragma unroll
                for (int nt = 0; nt < 4; nt++)
                    mma_tf32(acc[mt][nt], afr[mt], bfr[nt]);
        }
    }

    // epilogue
    #pragma unroll
    for (int mt = 0; mt < 4; mt++) {
        int r0 = wm * 64 + mt * 16 + grp;
        #pragma unroll
        for (int nt = 0; nt < 4; nt++) {
            int c0 = wn * 32 + nt * 8 + 2 * tig;
            float2 v0 = make_float2(acc[mt][nt][0] * alpha, acc[mt][nt][1] * alpha);
            float2 v1 = make_float2(acc[mt][nt][2] * alpha, acc[mt][nt][3] * alpha);
            *(float2*)(C + (long)r0 * ldc + c0)       = v0;
            *(float2*)(C + (long)(r0 + 8) * ldc + c0) = v1;
        }
    }
}

// =====================================================================
// tf32 mma.sync GEMM, NN variant:
//   C[M,N] = alpha * A[M,Kd] (row-major) * B[Kd,N] (row-major)
// Same tiling; B tile is [16 k][128 n] in smem.
// =====================================================================
__global__ void __launch_bounds__(256) gemm_nn_mma(
    const float* __restrict__ A, const float* __restrict__ B, float* __restrict__ C,
    int Kd, int lda, int ldb, int ldc, long sA, long sB, long sC, float alpha)
{
    __shared__ float As[128][SA_STRIDE];
    __shared__ float Bs[16][SB_STRIDE];

    const int tid  = threadIdx.x;
    const int wid  = tid >> 5;
    const int lane = tid & 31;
    const int wm   = wid & 1;
    const int wn   = wid >> 1;
    const int grp  = lane >> 2;
    const int tig  = lane & 3;

    A += (long)blockIdx.z * sA + (long)blockIdx.y * 128 * lda;
    B += (long)blockIdx.z * sB + (long)blockIdx.x * 128;          // column offset
    C += (long)blockIdx.z * sC + (long)blockIdx.y * 128 * ldc + (long)blockIdx.x * 128;

    const int arow = tid >> 1;
    const int acol = (tid & 1) * 8;
    const int brow = tid >> 4;           // 0..15
    const int bcol = (tid & 15) * 8;     // 0..120

    float acc[4][4][4];
    #pragma unroll
    for (int i = 0; i < 4; i++)
        #pragma unroll
        for (int j = 0; j < 4; j++)
            #pragma unroll
            for (int t = 0; t < 4; t++) acc[i][j][t] = 0.f;

    const int NCH = Kd >> 4;
    float4 pa0, pa1, pb0, pb1;
    pa0 = *(const float4*)(A + (long)arow * lda + acol);
    pa1 = *(const float4*)(A + (long)arow * lda + acol + 4);
    pb0 = *(const float4*)(B + (long)brow * ldb + bcol);
    pb1 = *(const float4*)(B + (long)brow * ldb + bcol + 4);

    for (int kc = 0; kc < NCH; kc++) {
        __syncthreads();
        *(float4*)&As[arow][acol]     = rna4(pa0);
        *(float4*)&As[arow][acol + 4] = rna4(pa1);
        *(float4*)&Bs[brow][bcol]     = rna4(pb0);
        *(float4*)&Bs[brow][bcol + 4] = rna4(pb1);
        __syncthreads();

        if (kc + 1 < NCH) {
            const float* An = A + (long)(kc + 1) * 16;
            const float* Bn = B + (long)(kc + 1) * 16 * ldb;
            pa0 = *(const float4*)(An + (long)arow * lda + acol);
            pa1 = *(const float4*)(An + (long)arow * lda + acol + 4);
            pb0 = *(const float4*)(Bn + (long)brow * ldb + bcol);
            pb1 = *(const float4*)(Bn + (long)brow * ldb + bcol + 4);
        }

        #pragma unroll
        for (int ks = 0; ks < 2; ks++) {
            const int k0 = ks * 8;
            uint32_t afr[4][4], bfr[4][2];
            #pragma unroll
            for (int mt = 0; mt < 4; mt++) {
                int r0 = wm * 64 + mt * 16 + grp;
                afr[mt][0] = __float_as_uint(As[r0][k0 + tig]);
                afr[mt][1] = __float_as_uint(As[r0 + 8][k0 + tig]);
                afr[mt][2] = __float_as_uint(As[r0][k0 + tig + 4]);
                afr[mt][3] = __float_as_uint(As[r0 + 8][k0 + tig + 4]);
            }
            #pragma unroll
            for (int nt = 0; nt < 4; nt++) {
                int n0 = wn * 32 + nt * 8 + grp;
                bfr[nt][0] = __float_as_uint(Bs[k0 + tig][n0]);
                bfr[nt][1] = __float_as_uint(Bs[k0 + tig + 4][n0]);
            }
            #pragma unroll
            for (int mt = 0; mt < 4; mt++)
                #pragma unroll
                for (int nt = 0; nt < 4; nt++)
                    mma_tf32(acc[mt][nt], afr[mt], bfr[nt]);
        }
    }

    #pragma unroll
    for (int mt = 0; mt < 4; mt++) {
        int r0 = wm * 64 + mt * 16 + grp;
        #pragma unroll
        for (int nt = 0; nt < 4; nt++) {
            int c0 = wn * 32 + nt * 8 + 2 * tig;
            float2 v0 = make_float2(acc[mt][nt][0] * alpha, acc[mt][nt][1] * alpha);
            float2 v1 = make_float2(acc[mt][nt][2] * alpha, acc[mt][nt][3] * alpha);
            *(float2*)(C + (long)r0 * ldc + c0)       = v0;
            *(float2*)(C + (long)(r0 + 8) * ldc + c0) = v1;
        }
    }
}

// ---------------- mask dtype detection ----------------
__global__ void detect_mask_kind(const unsigned char* __restrict__ m)
{
    if (threadIdx.x != 0 || blockIdx.x != 0) return;
    int cnt[4] = {0, 0, 0, 0};
    for (int i = 0; i < 4096; i++)
        if (m[i] != 0) cnt[i & 3]++;
    int kind;
    if (cnt[1] > 0)                    kind = 1;  // uint8 bool
    else if (cnt[2] > 0 || cnt[3] > 0) kind = 2;  // float32
    else                               kind = 0;  // int32 bool
    g_mask_kind = kind;
}

// ---------------- fused mask + softmax ----------------
__global__ void __launch_bounds__(256) mask_softmax(
    float* __restrict__ att, const void* __restrict__ mask_raw)
{
    long row = blockIdx.x;
    float* p = att + row * (long)NK;
    int tid = threadIdx.x;
    int kind = g_mask_kind;

    const unsigned char* m8  = (const unsigned char*)mask_raw + row * (long)NK;
    const int*           m32 = (const int*)mask_raw           + row * (long)NK;
    const float*         mf  = (const float*)mask_raw         + row * (long)NK;

    float v[8];
    float lmax = -INFINITY;
    #pragma unroll
    for (int i = 0; i < 8; i++) {
        int idx = tid + i * 256;
        bool keep;
        if (kind == 0)      keep = (m32[idx] != 0);
        else if (kind == 1) keep = (m8[idx] != 0);
        else                keep = (mf[idx] != 0.0f);
        float s = keep ? p[idx] : -INFINITY;
        v[i] = s;
        lmax = fmaxf(lmax, s);
    }

    __shared__ float red[8];
    #pragma unroll
    for (int o = 16; o > 0; o >>= 1)
        lmax = fmaxf(lmax, __shfl_xor_sync(0xffffffffu, lmax, o));
    if ((tid & 31) == 0) red[tid >> 5] = lmax;
    __syncthreads();
    float rmax = fmaxf(fmaxf(fmaxf(red[0], red[1]), fmaxf(red[2], red[3])),
                       fmaxf(fmaxf(red[4], red[5]), fmaxf(red[6], red[7])));
    __syncthreads();

    float lsum = 0.f;
    #pragma unroll
    for (int i = 0; i < 8; i++) {
        float e = (v[i] == -INFINITY) ? 0.f : __expf(v[i] - rmax);
        v[i] = e;
        lsum += e;
    }
    #pragma unroll
    for (int o = 16; o > 0; o >>= 1)
        lsum += __shfl_xor_sync(0xffffffffu, lsum, o);
    if ((tid & 31) == 0) red[tid >> 5] = lsum;
    __syncthreads();
    float rsum = red[0] + red[1] + red[2] + red[3] + red[4] + red[5] + red[6] + red[7];
    float inv = (rsum > 0.f) ? (1.f / rsum) : 0.f;

    #pragma unroll
    for (int i = 0; i < 8; i++) p[tid + i * 256] = v[i] * inv;
}

// ---------------- launcher ----------------
extern "C" void kernel_launch(void* const* d_in, const int* in_sizes, int n_in,
                              void* d_out, int out_size)
{
    const float* query = (const float*)d_in[0];   // [KQ, DIM]
    const float* key   = (const float*)d_in[1];   // [BATCH, NK, DIM]
    const float* W     = (const float*)d_in[2];   // [DIM, DIM]
    const void*  mask  = d_in[3];                 // [BATCH, KQ, NK] bool

    float* out_ptr = (float*)d_out;
    const long outBKD = (long)BATCH * KQ * DIM;

    float* qW;
    cudaGetSymbolAddress((void**)&qW, g_qW);
    float* att_ptr;
    if ((long)out_size > outBKD) {
        att_ptr = out_ptr + outBKD;
    } else {
        cudaGetSymbolAddress((void**)&att_ptr, g_att_scratch);
    }

    // 0) mask dtype detection
    detect_mask_kind<<<1, 1>>>((const unsigned char*)mask);

    // 1) qW = (query @ W) / 32      NN: A=query[512,1024], B=W[1024,1024]
    gemm_nn_mma<<<dim3(DIM / 128, KQ / 128, 1), 256>>>(
        query, W, qW, DIM, DIM, DIM, DIM, 0, 0, 0, 1.0f / 32.0f);

    // 2) att_raw[b] = qW @ key[b]^T NT: A=qW[512,1024], B=key[b][2048,1024]
    gemm_nt_mma<<<dim3(NK / 128, KQ / 128, BATCH), 256>>>(
        qW, key, att_ptr, DIM, DIM, DIM, NK,
        0L, (long)NK * DIM, (long)KQ * NK, 1.0f);

    // 3) mask + softmax in place
    mask_softmax<<<BATCH * KQ, 256>>>(att_ptr, mask);

    // 4) out[b] = att[b] @ key[b]   NN: A=att[b][512,2048], B=key[b][2048,1024]
    gemm_nn_mma<<<dim3(DIM / 128, KQ / 128, BATCH), 256>>>(
        att_ptr, key, out_ptr, NK, NK, DIM, DIM,
        (long)KQ * NK, (long)NK * DIM, (long)KQ * DIM, 1.0f);
}

// round 6
// speedup vs baseline: 3.2112x; 1.2863x over previous
#include <cuda_runtime.h>
#include <cuda_bf16.h>
#include <math.h>
#include <stdint.h>

// Problem shapes (fixed by the reference)
#define BATCH 16
#define KQ    512
#define NK    2048
#define DIM   1024

// ---------------- scratch (no cudaMalloc allowed) ----------------
__device__ float g_qW[KQ * DIM];                   // 2 MB
__device__ float g_att_scratch[BATCH * KQ * NK];   // 64 MB (if att not in d_out)
__device__ int   g_mask_kind;                      // 0=int32, 1=uint8, 2=float32

// ---------------- helpers ----------------
__device__ __forceinline__ float rna_tf32(float x) {
    float y;
    asm("cvt.rna.tf32.f32 %0, %1;" : "=f"(y) : "f"(x));
    return y;
}
__device__ __forceinline__ float4 rna4(float4 v) {
    v.x = rna_tf32(v.x); v.y = rna_tf32(v.y);
    v.z = rna_tf32(v.z); v.w = rna_tf32(v.w);
    return v;
}
__device__ __forceinline__ void mma_tf32(float* c, const uint32_t* a, const uint32_t* b) {
    asm volatile(
        "mma.sync.aligned.m16n8k8.row.col.f32.tf32.tf32.f32 "
        "{%0,%1,%2,%3}, {%4,%5,%6,%7}, {%8,%9}, {%0,%1,%2,%3};"
        : "+f"(c[0]), "+f"(c[1]), "+f"(c[2]), "+f"(c[3])
        : "r"(a[0]), "r"(a[1]), "r"(a[2]), "r"(a[3]), "r"(b[0]), "r"(b[1]));
}

#define PAD 20     // 16 k-cols + 4 pad -> conflict-free fragment LDS
#define SBS 136    // NN B tile: 128 n-cols + 8 pad

// =====================================================================
// tf32 mma.sync GEMM, NT: C[M,N] = alpha * A[M,Kd] * B[N,Kd]^T
// Block 128x128, 4 warps (2x2), warp tile 64x64, K-chunk 16,
// 2-stage smem double buffer, one barrier per chunk.
// =====================================================================
__global__ void __launch_bounds__(128) gemm_nt_mma(
    const float* __restrict__ A, const float* __restrict__ B, float* __restrict__ C,
    int Kd, int lda, int ldb, int ldc, long sA, long sB, long sC, float alpha)
{
    __shared__ float As[2][128][PAD];
    __shared__ float Bs[2][128][PAD];

    const int tid  = threadIdx.x;
    const int wid  = tid >> 5;
    const int lane = tid & 31;
    const int wm   = wid & 1;        // 0..1 -> 64-row half
    const int wn   = wid >> 1;       // 0..1 -> 64-col half
    const int grp  = lane >> 2;      // 0..7
    const int tig  = lane & 3;       // 0..3

    A += (long)blockIdx.z * sA + (long)blockIdx.y * 128 * lda;
    B += (long)blockIdx.z * sB + (long)blockIdx.x * 128 * ldb;
    C += (long)blockIdx.z * sC + (long)blockIdx.y * 128 * ldc + (long)blockIdx.x * 128;

    const int trow = tid >> 2;          // 0..31  (+32*i)
    const int tseg = (tid & 3) * 4;     // 0,4,8,12

    float acc[4][8][4];
    #pragma unroll
    for (int i = 0; i < 4; i++)
        #pragma unroll
        for (int j = 0; j < 8; j++)
            #pragma unroll
            for (int t = 0; t < 4; t++) acc[i][j][t] = 0.f;

    const int NCH = Kd >> 4;
    float4 pa[4], pb[4];

    // prologue: chunk 0 -> stage 0
    #pragma unroll
    for (int i = 0; i < 4; i++) {
        pa[i] = *(const float4*)(A + (long)(trow + 32 * i) * lda + tseg);
        pb[i] = *(const float4*)(B + (long)(trow + 32 * i) * ldb + tseg);
    }
    #pragma unroll
    for (int i = 0; i < 4; i++) {
        *(float4*)&As[0][trow + 32 * i][tseg] = rna4(pa[i]);
        *(float4*)&Bs[0][trow + 32 * i][tseg] = rna4(pb[i]);
    }
    __syncthreads();

    for (int kc = 0; kc < NCH; kc++) {
        const int st = kc & 1;
        if (kc + 1 < NCH) {
            const float* An = A + (long)(kc + 1) * 16;
            const float* Bn = B + (long)(kc + 1) * 16;
            #pragma unroll
            for (int i = 0; i < 4; i++) {
                pa[i] = *(const float4*)(An + (long)(trow + 32 * i) * lda + tseg);
                pb[i] = *(const float4*)(Bn + (long)(trow + 32 * i) * ldb + tseg);
            }
        }

        #pragma unroll
        for (int ks = 0; ks < 2; ks++) {
            const int k0 = ks * 8;
            uint32_t afr[4][4], bfr[8][2];
            #pragma unroll
            for (int mt = 0; mt < 4; mt++) {
                int r0 = wm * 64 + mt * 16 + grp;
                afr[mt][0] = __float_as_uint(As[st][r0][k0 + tig]);
                afr[mt][1] = __float_as_uint(As[st][r0 + 8][k0 + tig]);
                afr[mt][2] = __float_as_uint(As[st][r0][k0 + tig + 4]);
                afr[mt][3] = __float_as_uint(As[st][r0 + 8][k0 + tig + 4]);
            }
            #pragma unroll
            for (int nt = 0; nt < 8; nt++) {
                int n0 = wn * 64 + nt * 8 + grp;
                bfr[nt][0] = __float_as_uint(Bs[st][n0][k0 + tig]);
                bfr[nt][1] = __float_as_uint(Bs[st][n0][k0 + tig + 4]);
            }
            #pragma unroll
            for (int mt = 0; mt < 4; mt++)
                #pragma unroll
                for (int nt = 0; nt < 8; nt++)
                    mma_tf32(acc[mt][nt], afr[mt], bfr[nt]);
        }

        if (kc + 1 < NCH) {
            const int sn = st ^ 1;
            #pragma unroll
            for (int i = 0; i < 4; i++) {
                *(float4*)&As[sn][trow + 32 * i][tseg] = rna4(pa[i]);
                *(float4*)&Bs[sn][trow + 32 * i][tseg] = rna4(pb[i]);
            }
        }
        __syncthreads();
    }

    #pragma unroll
    for (int mt = 0; mt < 4; mt++) {
        int r0 = wm * 64 + mt * 16 + grp;
        #pragma unroll
        for (int nt = 0; nt < 8; nt++) {
            int c0 = wn * 64 + nt * 8 + 2 * tig;
            float2 v0 = make_float2(acc[mt][nt][0] * alpha, acc[mt][nt][1] * alpha);
            float2 v1 = make_float2(acc[mt][nt][2] * alpha, acc[mt][nt][3] * alpha);
            *(float2*)(C + (long)r0 * ldc + c0)       = v0;
            *(float2*)(C + (long)(r0 + 8) * ldc + c0) = v1;
        }
    }
}

// =====================================================================
// tf32 mma.sync GEMM, NN: C[M,N] = alpha * A[M,Kd] * B[Kd,N]
// Same tiling; B tile [16 k][128 n] per stage.
// =====================================================================
__global__ void __launch_bounds__(128) gemm_nn_mma(
    const float* __restrict__ A, const float* __restrict__ B, float* __restrict__ C,
    int Kd, int lda, int ldb, int ldc, long sA, long sB, long sC, float alpha)
{
    __shared__ float As[2][128][PAD];
    __shared__ float Bs[2][16][SBS];

    const int tid  = threadIdx.x;
    const int wid  = tid >> 5;
    const int lane = tid & 31;
    const int wm   = wid & 1;
    const int wn   = wid >> 1;
    const int grp  = lane >> 2;
    const int tig  = lane & 3;

    A += (long)blockIdx.z * sA + (long)blockIdx.y * 128 * lda;
    B += (long)blockIdx.z * sB + (long)blockIdx.x * 128;
    C += (long)blockIdx.z * sC + (long)blockIdx.y * 128 * ldc + (long)blockIdx.x * 128;

    const int trow = tid >> 2;
    const int tseg = (tid & 3) * 4;
    const int brow = tid >> 5;          // 0..3 (+4*i)
    const int bcol = (tid & 31) * 4;    // 0..124

    float acc[4][8][4];
    #pragma unroll
    for (int i = 0; i < 4; i++)
        #pragma unroll
        for (int j = 0; j < 8; j++)
            #pragma unroll
            for (int t = 0; t < 4; t++) acc[i][j][t] = 0.f;

    const int NCH = Kd >> 4;
    float4 pa[4], pb[4];

    #pragma unroll
    for (int i = 0; i < 4; i++) {
        pa[i] = *(const float4*)(A + (long)(trow + 32 * i) * lda + tseg);
        pb[i] = *(const float4*)(B + (long)(brow + 4 * i) * ldb + bcol);
    }
    #pragma unroll
    for (int i = 0; i < 4; i++) {
        *(float4*)&As[0][trow + 32 * i][tseg] = rna4(pa[i]);
        *(float4*)&Bs[0][brow + 4 * i][bcol]  = rna4(pb[i]);
    }
    __syncthreads();

    for (int kc = 0; kc < NCH; kc++) {
        const int st = kc & 1;
        if (kc + 1 < NCH) {
            const float* An = A + (long)(kc + 1) * 16;
            const float* Bn = B + (long)(kc + 1) * 16 * ldb;
            #pragma unroll
            for (int i = 0; i < 4; i++) {
                pa[i] = *(const float4*)(An + (long)(trow + 32 * i) * lda + tseg);
                pb[i] = *(const float4*)(Bn + (long)(brow + 4 * i) * ldb + bcol);
            }
        }

        #pragma unroll
        for (int ks = 0; ks < 2; ks++) {
            const int k0 = ks * 8;
            uint32_t afr[4][4], bfr[8][2];
            #pragma unroll
            for (int mt = 0; mt < 4; mt++) {
                int r0 = wm * 64 + mt * 16 + grp;
                afr[mt][0] = __float_as_uint(As[st][r0][k0 + tig]);
                afr[mt][1] = __float_as_uint(As[st][r0 + 8][k0 + tig]);
                afr[mt][2] = __float_as_uint(As[st][r0][k0 + tig + 4]);
                afr[mt][3] = __float_as_uint(As[st][r0 + 8][k0 + tig + 4]);
            }
            #pragma unroll
            for (int nt = 0; nt < 8; nt++) {
                int n0 = wn * 64 + nt * 8 + grp;
                bfr[nt][0] = __float_as_uint(Bs[st][k0 + tig][n0]);
                bfr[nt][1] = __float_as_uint(Bs[st][k0 + tig + 4][n0]);
            }
            #pragma unroll
            for (int mt = 0; mt < 4; mt++)
                #pragma unroll
                for (int nt = 0; nt < 8; nt++)
                    mma_tf32(acc[mt][nt], afr[mt], bfr[nt]);
        }

        if (kc + 1 < NCH) {
            const int sn = st ^ 1;
            #pragma unroll
            for (int i = 0; i < 4; i++) {
                *(float4*)&As[sn][trow + 32 * i][tseg] = rna4(pa[i]);
                *(float4*)&Bs[sn][brow + 4 * i][bcol]  = rna4(pb[i]);
            }
        }
        __syncthreads();
    }

    #pragma unroll
    for (int mt = 0; mt < 4; mt++) {
        int r0 = wm * 64 + mt * 16 + grp;
        #pragma unroll
        for (int nt = 0; nt < 8; nt++) {
            int c0 = wn * 64 + nt * 8 + 2 * tig;
            float2 v0 = make_float2(acc[mt][nt][0] * alpha, acc[mt][nt][1] * alpha);
            float2 v1 = make_float2(acc[mt][nt][2] * alpha, acc[mt][nt][3] * alpha);
            *(float2*)(C + (long)r0 * ldc + c0)       = v0;
            *(float2*)(C + (long)(r0 + 8) * ldc + c0) = v1;
        }
    }
}

// ---------------- mask dtype detection ----------------
__global__ void detect_mask_kind(const unsigned char* __restrict__ m)
{
    if (threadIdx.x != 0 || blockIdx.x != 0) return;
    int cnt[4] = {0, 0, 0, 0};
    for (int i = 0; i < 4096; i++)
        if (m[i] != 0) cnt[i & 3]++;
    int kind;
    if (cnt[1] > 0)                    kind = 1;  // uint8 bool
    else if (cnt[2] > 0 || cnt[3] > 0) kind = 2;  // float32
    else                               kind = 0;  // int32 bool
    g_mask_kind = kind;
}

// ---------------- fused mask + softmax ----------------
__global__ void __launch_bounds__(256) mask_softmax(
    float* __restrict__ att, const void* __restrict__ mask_raw)
{
    long row = blockIdx.x;
    float* p = att + row * (long)NK;
    int tid = threadIdx.x;
    int kind = g_mask_kind;

    const unsigned char* m8  = (const unsigned char*)mask_raw + row * (long)NK;
    const int*           m32 = (const int*)mask_raw           + row * (long)NK;
    const float*         mf  = (const float*)mask_raw         + row * (long)NK;

    float v[8];
    float lmax = -INFINITY;
    #pragma unroll
    for (int i = 0; i < 8; i++) {
        int idx = tid + i * 256;
        bool keep;
        if (kind == 0)      keep = (m32[idx] != 0);
        else if (kind == 1) keep = (m8[idx] != 0);
        else                keep = (mf[idx] != 0.0f);
        float s = keep ? p[idx] : -INFINITY;
        v[i] = s;
        lmax = fmaxf(lmax, s);
    }

    __shared__ float red[8];
    #pragma unroll
    for (int o = 16; o > 0; o >>= 1)
        lmax = fmaxf(lmax, __shfl_xor_sync(0xffffffffu, lmax, o));
    if ((tid & 31) == 0) red[tid >> 5] = lmax;
    __syncthreads();
    float rmax = fmaxf(fmaxf(fmaxf(red[0], red[1]), fmaxf(red[2], red[3])),
                       fmaxf(fmaxf(red[4], red[5]), fmaxf(red[6], red[7])));
    __syncthreads();

    float lsum = 0.f;
    #pragma unroll
    for (int i = 0; i < 8; i++) {
        float e = (v[i] == -INFINITY) ? 0.f : __expf(v[i] - rmax);
        v[i] = e;
        lsum += e;
    }
    #pragma unroll
    for (int o = 16; o > 0; o >>= 1)
        lsum += __shfl_xor_sync(0xffffffffu, lsum, o);
    if ((tid & 31) == 0) red[tid >> 5] = lsum;
    __syncthreads();
    float rsum = red[0] + red[1] + red[2] + red[3] + red[4] + red[5] + red[6] + red[7];
    float inv = (rsum > 0.f) ? (1.f / rsum) : 0.f;

    #pragma unroll
    for (int i = 0; i < 8; i++) p[tid + i * 256] = v[i] * inv;
}

// ---------------- launcher ----------------
extern "C" void kernel_launch(void* const* d_in, const int* in_sizes, int n_in,
                              void* d_out, int out_size)
{
    const float* query = (const float*)d_in[0];   // [KQ, DIM]
    const float* key   = (const float*)d_in[1];   // [BATCH, NK, DIM]
    const float* W     = (const float*)d_in[2];   // [DIM, DIM]
    const void*  mask  = d_in[3];                 // [BATCH, KQ, NK] bool

    float* out_ptr = (float*)d_out;
    const long outBKD = (long)BATCH * KQ * DIM;

    float* qW;
    cudaGetSymbolAddress((void**)&qW, g_qW);
    float* att_ptr;
    if ((long)out_size > outBKD) {
        att_ptr = out_ptr + outBKD;
    } else {
        cudaGetSymbolAddress((void**)&att_ptr, g_att_scratch);
    }

    // 0) mask dtype detection
    detect_mask_kind<<<1, 1>>>((const unsigned char*)mask);

    // 1) qW = (query @ W) / 32      NN
    gemm_nn_mma<<<dim3(DIM / 128, KQ / 128, 1), 128>>>(
        query, W, qW, DIM, DIM, DIM, DIM, 0, 0, 0, 1.0f / 32.0f);

    // 2) att_raw[b] = qW @ key[b]^T NT
    gemm_nt_mma<<<dim3(NK / 128, KQ / 128, BATCH), 128>>>(
        qW, key, att_ptr, DIM, DIM, DIM, NK,
        0L, (long)NK * DIM, (long)KQ * NK, 1.0f);

    // 3) mask + softmax in place
    mask_softmax<<<BATCH * KQ, 256>>>(att_ptr, mask);

    // 4) out[b] = att[b] @ key[b]   NN
    gemm_nn_mma<<<dim3(DIM / 128, KQ / 128, BATCH), 128>>>(
        att_ptr, key, out_ptr, NK, NK, DIM, DIM,
        (long)KQ * NK, (long)NK * DIM, (long)KQ * DIM, 1.0f);
}